// round 16
// baseline (speedup 1.0000x reference)
#include <cuda_runtime.h>
#include <cuda_fp16.h>
#include <math.h>
#include <stdint.h>
#include <string.h>

#define Bsz 32
#define Ssz 512
#define Tsz 180
#define Dsz 512
#define Fsz 2048
#define Lsz 6
#define Hsz 8
#define DHsz 64

// ---------------- scratch (fp32) ----------------
__device__ float g_h   [Bsz*Ssz*Dsz];
__device__ float g_tmp [Bsz*Ssz*Dsz];
__device__ float g_q   [Bsz*Ssz*Dsz];
__device__ float g_ffn [Bsz*Ssz*Fsz];
__device__ float g_d   [Bsz*Tsz*Dsz];
__device__ float g_dq  [Bsz*Tsz*Dsz];
__device__ float g_dtmp[Bsz*Tsz*Dsz];
// ---------------- fp16 shadows ----------------
__device__ __half g_h16   [Bsz*Ssz*Dsz];
__device__ __half g_tmp16 [Bsz*Ssz*Dsz];
__device__ __half g_ffn16 [Bsz*Ssz*Fsz];
__device__ __half g_d16   [Bsz*Tsz*Dsz];
__device__ __half g_dtmp16[Bsz*Tsz*Dsz];
__device__ __half g_dq16  [Bsz*Tsz*Dsz];
__device__ __half g_qkv16 [Bsz*Ssz*3*Dsz];
__device__ __half g_kv16  [Bsz*Ssz*2*Dsz];
// ---------------- fp16 weights ----------------
__device__ __half g_w16_e1[Lsz*Dsz*Fsz];
__device__ __half g_w16_e2[Lsz*Fsz*Dsz];
__device__ __half g_w16_d1[Lsz*Dsz*Fsz];
__device__ __half g_w16_d2[Lsz*Fsz*Dsz];
__device__ __half g_wqkv_e [Lsz*Dsz*3*Dsz];
__device__ __half g_wqkv_ds[Lsz*Dsz*3*Dsz];
__device__ __half g_wkv_dc [Lsz*Dsz*2*Dsz];
__device__ __half g_wo_e  [Lsz*Dsz*Dsz];
__device__ __half g_wo_ds [Lsz*Dsz*Dsz];
__device__ __half g_wq_dc [Lsz*Dsz*Dsz];
__device__ __half g_wo_dc [Lsz*Dsz*Dsz];

// ---------------- helpers ----------------
__device__ __forceinline__ float warpSum(float v) {
    #pragma unroll
    for (int o = 16; o; o >>= 1) v += __shfl_xor_sync(0xffffffffu, v, o);
    return v;
}
__device__ __forceinline__ float warpMax(float v) {
    #pragma unroll
    for (int o = 16; o; o >>= 1) v = fmaxf(v, __shfl_xor_sync(0xffffffffu, v, o));
    return v;
}
__device__ __forceinline__ uint32_t s2u(const void* p) {
    return (uint32_t)__cvta_generic_to_shared(p);
}
__device__ __forceinline__ uint32_t h2u(__half2 h) {
    uint32_t u;
    memcpy(&u, &h, 4);
    return u;
}
__device__ __forceinline__ uint32_t pack_h2(float a, float b) {
    return h2u(__floats2half2_rn(a, b));
}
#define MMA_F16(c, a, b) \
    asm volatile("mma.sync.aligned.m16n8k16.row.col.f32.f16.f16.f32 " \
        "{%0,%1,%2,%3}, {%4,%5,%6,%7}, {%8,%9}, {%0,%1,%2,%3};" \
        : "+f"((c)[0]), "+f"((c)[1]), "+f"((c)[2]), "+f"((c)[3]) \
        : "r"((a)[0]), "r"((a)[1]), "r"((a)[2]), "r"((a)[3]), \
          "r"((b)[0]), "r"((b)[1]))
#define LDSM_X4(r, addr) \
    asm volatile("ldmatrix.sync.aligned.m8n8.x4.shared.b16 {%0,%1,%2,%3}, [%4];" \
        : "=r"((r)[0]), "=r"((r)[1]), "=r"((r)[2]), "=r"((r)[3]) : "r"(addr))
#define LDSM_X4T(r, addr) \
    asm volatile("ldmatrix.sync.aligned.m8n8.x4.trans.shared.b16 {%0,%1,%2,%3}, [%4];" \
        : "=r"((r)[0]), "=r"((r)[1]), "=r"((r)[2]), "=r"((r)[3]) : "r"(addr))
#define CP16(smem_addr, gptr) \
    asm volatile("cp.async.cg.shared.global [%0], [%1], 16;" \
        :: "r"(smem_addr), "l"(gptr) : "memory")
#define CP_COMMIT() asm volatile("cp.async.commit_group;" ::: "memory")
#define CP_WAIT0()  asm volatile("cp.async.wait_group 0;" ::: "memory")

// ---------------- fp32 -> fp16 conversions -------------------------------------------
__global__ __launch_bounds__(256) void f2h_kernel(
    const float* __restrict__ src, __half* __restrict__ dst, int n)
{
    const int i = (blockIdx.x * 256 + threadIdx.x) * 8;
    if (i >= n) return;
    float4 a = *(const float4*)(src + i);
    float4 b = *(const float4*)(src + i + 4);
    uint4 o;
    o.x = pack_h2(a.x, a.y);
    o.y = pack_h2(a.z, a.w);
    o.z = pack_h2(b.x, b.y);
    o.w = pack_h2(b.z, b.w);
    *(uint4*)(dst + i) = o;
}
// fuse nmat [512,512] matrices (starting at matBase within [4,512,512]) into [512, nmat*512]
__global__ __launch_bounds__(256) void f2h_fuse(
    const float* __restrict__ src, __half* __restrict__ dst, int matBase, int nmat)
{
    const int l = blockIdx.z;
    const int rowCols = nmat * 512;
    const int idx = (blockIdx.x * 256 + threadIdx.x) * 8;
    if (idx >= 512 * rowCols) return;
    const int k = idx / rowCols, j = idx % rowCols;
    const int mat = j >> 9, jj = j & 511;
    const float* s = src + (size_t)l * 4 * Dsz * Dsz
                   + (size_t)(matBase + mat) * Dsz * Dsz + k * 512 + jj;
    float4 a = *(const float4*)s;
    float4 b = *(const float4*)(s + 4);
    uint4 o;
    o.x = pack_h2(a.x, a.y);
    o.y = pack_h2(a.z, a.w);
    o.z = pack_h2(b.x, b.y);
    o.w = pack_h2(b.z, b.w);
    *(uint4*)(dst + (size_t)l * 512 * rowCols + idx) = o;
}

// ---------------- FP16 GEMM: cp.async pair-double-buffer (BK=64/barrier) -------------
#define ARS 20
#define BRS 68
#define STAGES 4
#define A_STG (128 * ARS)
#define B_STG (32 * BRS)
#define GSMEM ((A_STG + B_STG) * STAGES * 4)

__device__ __forceinline__ void mma_half(uint32_t aAddr, uint32_t bAddr, int kk,
                                         float acc[4][4][4])
{
    uint32_t af[4][4], bf[2][4];
    #pragma unroll
    for (int mt = 0; mt < 4; mt++)
        LDSM_X4(af[mt], aAddr + kk * 32 + mt * 1280);
    #pragma unroll
    for (int nt2 = 0; nt2 < 2; nt2++)
        LDSM_X4T(bf[nt2], bAddr + kk * 4352 + nt2 * 32);
    #pragma unroll
    for (int mt = 0; mt < 4; mt++)
        #pragma unroll
        for (int nt = 0; nt < 4; nt++)
            MMA_F16(acc[mt][nt], af[mt], &bf[nt >> 1][(nt & 1) * 2]);
}

__global__ __launch_bounds__(256, 2) void gemm_f16(
    const __half* __restrict__ A16, const __half* __restrict__ B16,
    const float* __restrict__ bias, float* __restrict__ C,
    __half* __restrict__ C16, int M, int N, int K, int doRelu)
{
    extern __shared__ uint32_t smg[];
    uint32_t* As = smg;
    uint32_t* Bs = smg + STAGES * A_STG;

    const int tid = threadIdx.x, lane = tid & 31, warp = tid >> 5;
    const int g = lane >> 2, t4 = lane & 3;
    const int wm = (warp >> 2) << 6, wn = (warp & 3) << 5;
    const int bm = blockIdx.y << 7, bn = blockIdx.x << 7;

    const int ar  = tid >> 1;
    const int bkr = tid >> 3;
    const __half* aSrc = A16 + (size_t)(bm + ar) * K + ((tid & 1) << 4);
    const __half* bSrc = B16 + (size_t)bkr * N + bn + ((tid & 7) << 4);
    const uint32_t aDst = s2u(&As[ar * ARS + ((tid & 1) << 3)]);
    const uint32_t bDst = s2u(&Bs[bkr * BRS + ((tid & 7) << 3)]);

    const int aRow = wm + ((lane >> 3) & 1) * 8 + (lane & 7);
    const int aCol = (lane >> 4) * 4;
    const int bRow = ((lane >> 3) & 1) * 8 + (lane & 7);
    const int bCol = (wn >> 1) + (lane >> 4) * 4;
    uint32_t aAddrS[STAGES], bAddrS[STAGES];
    #pragma unroll
    for (int s = 0; s < STAGES; s++) {
        aAddrS[s] = s2u(&As[s * A_STG + aRow * ARS + aCol]);
        bAddrS[s] = s2u(&Bs[s * B_STG + bRow * BRS + bCol]);
    }

    const int nc = K >> 5;   // chunks (even)
    const int np = nc >> 1;  // pairs
    float acc[4][4][4] = {};

    // prologue: load pair 0 (chunks 0,1 -> stages 0,1)
    #pragma unroll
    for (int j = 0; j < 2; j++) {
        const __half* ap = aSrc + j * 32;
        const __half* bp = bSrc + (size_t)j * 32 * N;
        CP16(aDst + j * (A_STG * 4),      ap);
        CP16(aDst + j * (A_STG * 4) + 16, ap + 8);
        CP16(bDst + j * (B_STG * 4),      bp);
        CP16(bDst + j * (B_STG * 4) + 16, bp + 8);
    }
    CP_COMMIT();
    CP_WAIT0();
    __syncthreads();

    for (int p = 0; p < np; p++) {
        // prefetch pair p+1 into the opposite pair's stages (consumed & barrier-sealed)
        const int more = (p + 1 < np);
        if (more) {
            #pragma unroll
            for (int j = 0; j < 2; j++) {
                const int ch = 2 * p + 2 + j;
                const int st = ch & 3;
                const __half* ap = aSrc + ch * 32;
                const __half* bp = bSrc + (size_t)ch * 32 * N;
                CP16(aDst + st * (A_STG * 4),      ap);
                CP16(aDst + st * (A_STG * 4) + 16, ap + 8);
                CP16(bDst + st * (B_STG * 4),      bp);
                CP16(bDst + st * (B_STG * 4) + 16, bp + 8);
            }
            CP_COMMIT();
        }
        // compute resident pair
        const int s0 = (2 * p) & 3, s1 = s0 + 1;
        mma_half(aAddrS[s0], bAddrS[s0], 0, acc);
        mma_half(aAddrS[s0], bAddrS[s0], 1, acc);
        mma_half(aAddrS[s1], bAddrS[s1], 0, acc);
        mma_half(aAddrS[s1], bAddrS[s1], 1, acc);

        if (more) {
            CP_WAIT0();
            __syncthreads();
        }
    }

    #pragma unroll
    for (int mt = 0; mt < 4; mt++) {
        const int gm = bm + wm + mt * 16 + g;
        #pragma unroll
        for (int nt = 0; nt < 4; nt++) {
            const int gn = bn + wn + nt * 8 + (t4 << 1);
            const float b0v = bias[gn], b1v = bias[gn + 1];
            float2 o0 = make_float2(acc[mt][nt][0] + b0v, acc[mt][nt][1] + b1v);
            float2 o1 = make_float2(acc[mt][nt][2] + b0v, acc[mt][nt][3] + b1v);
            if (doRelu) {
                o0.x = fmaxf(o0.x, 0.f); o0.y = fmaxf(o0.y, 0.f);
                o1.x = fmaxf(o1.x, 0.f); o1.y = fmaxf(o1.y, 0.f);
            }
            if (C) {
                *(float2*)(C + (size_t)gm * N + gn)       = o0;
                *(float2*)(C + (size_t)(gm + 8) * N + gn) = o1;
            }
            if (C16) {
                *(uint32_t*)(C16 + (size_t)gm * N + gn)       = pack_h2(o0.x, o0.y);
                *(uint32_t*)(C16 + (size_t)(gm + 8) * N + gn) = pack_h2(o1.x, o1.y);
            }
        }
    }
}

// ---------------- fp16 flash attention (per-tensor row strides) ----------------------
#define ATT_SMEM (13760 * 4)
__global__ __launch_bounds__(256) void attn_f16(
    const __half* __restrict__ Q, int ldq,
    const __half* __restrict__ K, int ldk,
    const __half* __restrict__ V, int ldv,
    __half* __restrict__ O16, int Sq, int Sk, int causal)
{
    extern __shared__ uint32_t sm32[];
    uint32_t* Qs = sm32;
    uint32_t* Ks = sm32 + 2304;
    uint32_t* Vs = sm32 + 4608;
    float*    Ss = (float*)(sm32 + 6912);
    uint32_t* Pb = sm32 + 11264;
    float* m_row = (float*)(sm32 + 13568);
    float* s_row = m_row + 64;
    float* f_row = s_row + 64;

    const int tid = threadIdx.x, lane = tid & 31, w = tid >> 5;
    const int wm = w & 3, wn = w >> 2;
    const int g = lane >> 2, t4 = lane & 3;
    const int qbase = blockIdx.x * 64;
    const int h = blockIdx.y, b = blockIdx.z;
    const size_t hoff = (size_t)h * DHsz;

    const int srow = tid >> 2;
    const int sseg = (tid & 3) << 3;

    {
        const int qg = qbase + srow;
        uint4 v0 = make_uint4(0, 0, 0, 0), v1 = v0;
        if (qg < Sq) {
            const __half* src = Q + (size_t)(b * Sq + qg) * ldq + hoff + (sseg << 1);
            v0 = *(const uint4*)(src);
            v1 = *(const uint4*)(src + 8);
        }
        *(uint4*)&Qs[srow * 36 + sseg]     = v0;
        *(uint4*)&Qs[srow * 36 + sseg + 4] = v1;
    }
    if (tid < 64) { m_row[tid] = -1e30f; s_row[tid] = 0.f; }
    __syncthreads();

    const int aRow = wm * 16 + ((lane >> 3) & 1) * 8 + (lane & 7);
    const int aCol = (lane >> 4) * 4;
    const uint32_t qAddr = s2u(&Qs[aRow * 36 + aCol]);
    uint32_t qf[4][4];
    #pragma unroll
    for (int kc = 0; kc < 4; kc++)
        LDSM_X4(qf[kc], qAddr + kc * 32);

    const uint32_t pAddr = s2u(&Pb[aRow * 36 + aCol]);
    const int bRow = ((lane >> 3) & 1) * 8 + (lane & 7);
    const int bCol = wn * 16 + (lane >> 4) * 4;
    const uint32_t vAddr = s2u(&Vs[bRow * 36 + bCol]);

    float acc_o[4][4] = {};
    const int qend = qbase + 63;
    const int qr = wm * 16 + g;

    for (int c0 = 0; c0 < Sk; c0 += 64) {
        if (causal && c0 > qend) break;
        {
            const int kg = c0 + srow;
            uint4 k0 = make_uint4(0, 0, 0, 0), k1 = k0, v0 = k0, v1 = k0;
            if (kg < Sk) {
                const __half* ks = K + (size_t)(b * Sk + kg) * ldk + hoff + (sseg << 1);
                const __half* vs = V + (size_t)(b * Sk + kg) * ldv + hoff + (sseg << 1);
                k0 = *(const uint4*)(ks); k1 = *(const uint4*)(ks + 8);
                v0 = *(const uint4*)(vs); v1 = *(const uint4*)(vs + 8);
            }
            *(uint4*)&Ks[srow * 36 + sseg]     = k0;
            *(uint4*)&Ks[srow * 36 + sseg + 4] = k1;
            *(uint4*)&Vs[srow * 36 + sseg]     = v0;
            *(uint4*)&Vs[srow * 36 + sseg + 4] = v1;
        }
        __syncthreads();

        float acc_s[4][4] = {};
        #pragma unroll
        for (int kc = 0; kc < 4; kc++) {
            #pragma unroll
            for (int nt = 0; nt < 4; nt++) {
                const int key = wn * 32 + nt * 8 + g;
                uint32_t bf[2];
                bf[0] = Ks[key * 36 + kc * 8 + t4];
                bf[1] = Ks[key * 36 + kc * 8 + t4 + 4];
                MMA_F16(acc_s[nt], qf[kc], bf);
            }
        }
        {
            const int qg0 = qbase + qr, qg1 = qg0 + 8;
            #pragma unroll
            for (int nt = 0; nt < 4; nt++) {
                const int cl = wn * 32 + nt * 8 + (t4 << 1);
                const int kg = c0 + cl;
                float s00 = acc_s[nt][0] * 0.125f, s01 = acc_s[nt][1] * 0.125f;
                float s10 = acc_s[nt][2] * 0.125f, s11 = acc_s[nt][3] * 0.125f;
                if (kg >= Sk || (causal && kg > qg0)) s00 = -1e30f;
                if (kg + 1 >= Sk || (causal && kg + 1 > qg0)) s01 = -1e30f;
                if (kg >= Sk || (causal && kg > qg1)) s10 = -1e30f;
                if (kg + 1 >= Sk || (causal && kg + 1 > qg1)) s11 = -1e30f;
                Ss[qr * 68 + cl] = s00;        Ss[qr * 68 + cl + 1] = s01;
                Ss[(qr + 8) * 68 + cl] = s10;  Ss[(qr + 8) * 68 + cl + 1] = s11;
            }
        }
        __syncthreads();

        #pragma unroll
        for (int rr = 0; rr < 8; rr++) {
            const int r = w * 8 + rr;
            float s0v = Ss[r * 68 + lane];
            float s1v = Ss[r * 68 + lane + 32];
            const float mx = warpMax(fmaxf(s0v, s1v));
            const float mold = m_row[r];
            const float mnew = fmaxf(mold, mx);
            float p0 = __expf(s0v - mnew);
            float p1 = __expf(s1v - mnew);
            const float sum = warpSum(p0 + p1);
            ((__half*)Pb)[r * 72 + lane]      = __float2half_rn(p0);
            ((__half*)Pb)[r * 72 + lane + 32] = __float2half_rn(p1);
            if (lane == 0) {
                const float f = __expf(mold - mnew);
                f_row[r] = f;
                s_row[r] = s_row[r] * f + sum;
                m_row[r] = mnew;
            }
        }
        __syncthreads();

        {
            const float f0 = f_row[qr], f1 = f_row[qr + 8];
            #pragma unroll
            for (int nt = 0; nt < 4; nt++) {
                acc_o[nt][0] *= f0; acc_o[nt][1] *= f0;
                acc_o[nt][2] *= f1; acc_o[nt][3] *= f1;
            }
        }
        #pragma unroll
        for (int kc = 0; kc < 4; kc++) {
            uint32_t pf[4], vf[2][4];
            LDSM_X4(pf, pAddr + kc * 32);
            LDSM_X4T(vf[0], vAddr + kc * 2304);
            LDSM_X4T(vf[1], vAddr + kc * 2304 + 32);
            #pragma unroll
            for (int nt = 0; nt < 4; nt++)
                MMA_F16(acc_o[nt], pf, &vf[nt >> 1][(nt & 1) * 2]);
        }
        __syncthreads();
    }

    const float inv0 = 1.f / s_row[qr];
    const float inv1 = 1.f / s_row[qr + 8];
    const int qg0 = qbase + qr, qg1 = qg0 + 8;
    #pragma unroll
    for (int nt = 0; nt < 4; nt++) {
        const int dcol = wn * 32 + nt * 8 + (t4 << 1);
        if (qg0 < Sq)
            *(uint32_t*)(O16 + (size_t)(b * Sq + qg0) * Dsz + hoff + dcol) =
                pack_h2(acc_o[nt][0] * inv0, acc_o[nt][1] * inv0);
        if (qg1 < Sq)
            *(uint32_t*)(O16 + (size_t)(b * Sq + qg1) * Dsz + hoff + dcol) =
                pack_h2(acc_o[nt][2] * inv1, acc_o[nt][3] * inv1);
    }
}

// ---------------- residual + LayerNorm (+ fp16 copy) --------------------------------
__global__ __launch_bounds__(128) void add_ln_kernel(
    float* __restrict__ h, const float* __restrict__ r,
    const float* __restrict__ scale, const float* __restrict__ bias,
    __half* __restrict__ h16)
{
    const int row = blockIdx.x;
    const int tid = threadIdx.x;
    const int lane = tid & 31, warp = tid >> 5;
    float* hp = h + (size_t)row * Dsz;
    const float* rp = r + (size_t)row * Dsz;

    float4 hv = *(const float4*)(hp + tid * 4);
    float4 rv = *(const float4*)(rp + tid * 4);
    float v0 = hv.x + rv.x, v1 = hv.y + rv.y, v2 = hv.z + rv.z, v3 = hv.w + rv.w;

    float sum = v0 + v1 + v2 + v3;
    float sq  = v0*v0 + v1*v1 + v2*v2 + v3*v3;
    sum = warpSum(sum); sq = warpSum(sq);

    __shared__ float s1[4], s2[4];
    if (lane == 0) { s1[warp] = sum; s2[warp] = sq; }
    __syncthreads();
    sum = s1[0] + s1[1] + s1[2] + s1[3];
    sq  = s2[0] + s2[1] + s2[2] + s2[3];

    const float mu = sum * (1.f / Dsz);
    const float var = sq * (1.f / Dsz) - mu * mu;
    const float rs = rsqrtf(var + 1e-5f);

    float4 sc4 = *(const float4*)(scale + tid * 4);
    float4 bi4 = *(const float4*)(bias + tid * 4);
    float4 o;
    o.x = (v0 - mu) * rs * sc4.x + bi4.x;
    o.y = (v1 - mu) * rs * sc4.y + bi4.y;
    o.z = (v2 - mu) * rs * sc4.z + bi4.z;
    o.w = (v3 - mu) * rs * sc4.w + bi4.w;
    *(float4*)(hp + tid * 4) = o;
    uint2 p;
    p.x = pack_h2(o.x, o.y);
    p.y = pack_h2(o.z, o.w);
    *(uint2*)(h16 + (size_t)row * Dsz + tid * 4) = p;
}

// ---------------- embeddings (+ fp16 copy) -------------------------------------------
__device__ __forceinline__ float pos_enc(int pos, int d) {
    const int i2 = d & ~1;
    const float freq = expf(-(float)i2 * (9.210340371976184f / 512.f));
    const float ang = (float)pos * freq;
    return (d & 1) ? cosf(ang) : sinf(ang);
}
__global__ __launch_bounds__(512) void embed_src_kernel(
    const float* __restrict__ x, const float* __restrict__ w,
    const float* __restrict__ b, float* __restrict__ h, __half* __restrict__ h16)
{
    const int token = blockIdx.x;
    const int d = threadIdx.x;
    const int s = token % Ssz;
    const float x0 = x[token * 2 + 0], x1 = x[token * 2 + 1];
    const float val = x0 * w[d] + x1 * w[Dsz + d] + b[d] + pos_enc(s, d);
    h[(size_t)token * Dsz + d] = val;
    h16[(size_t)token * Dsz + d] = __float2half_rn(val);
}
__global__ __launch_bounds__(512) void embed_tgt_kernel(
    const float* __restrict__ y, const float* __restrict__ w,
    const float* __restrict__ b, float* __restrict__ dd, __half* __restrict__ d16)
{
    const int token = blockIdx.x;
    const int d = threadIdx.x;
    const int bb = token / Tsz, t = token % Tsz;
    const float val = (t == 0) ? 0.f : y[bb * Tsz + (t - 1)];
    const float o = val * w[d] + b[d] + pos_enc(t, d);
    dd[(size_t)token * Dsz + d] = o;
    d16[(size_t)token * Dsz + d] = __float2half_rn(o);
}

// ---------------- final projection ---------------------------------------------------
__global__ __launch_bounds__(128) void out_proj_kernel(
    const float* __restrict__ dd, const float* __restrict__ w,
    const float* __restrict__ b, float* __restrict__ out)
{
    const int token = blockIdx.x;
    const int tid = threadIdx.x;
    const int lane = tid & 31, warp = tid >> 5;
    float s = 0.f;
    for (int i = tid; i < Dsz; i += 128)
        s += dd[(size_t)token * Dsz + i] * w[i];
    s = warpSum(s);
    __shared__ float smr[4];
    if (lane == 0) smr[warp] = s;
    __syncthreads();
    if (tid == 0) out[token] = smr[0] + smr[1] + smr[2] + smr[3] + b[0];
}

// ---------------- host orchestration -------------------------------------------------
extern "C" void kernel_launch(void* const* d_in, const int* in_sizes, int n_in,
                              void* d_out, int out_size)
{
    const float* x          = (const float*)d_in[0];
    const float* y          = (const float*)d_in[1];
    const float* src_w      = (const float*)d_in[2];
    const float* src_b      = (const float*)d_in[3];
    const float* tgt_w      = (const float*)d_in[4];
    const float* tgt_b      = (const float*)d_in[5];
    const float* enc_attn_w = (const float*)d_in[6];
    const float* enc_attn_b = (const float*)d_in[7];
    const float* enc_ffn_w1 = (const float*)d_in[8];
    const float* enc_ffn_b1 = (const float*)d_in[9];
    const float* enc_ffn_w2 = (const float*)d_in[10];
    const float* enc_ffn_b2 = (const float*)d_in[11];
    const float* enc_ln_s   = (const float*)d_in[12];
    const float* enc_ln_b   = (const float*)d_in[13];
    const float* dec_self_w = (const float*)d_in[14];
    const float* dec_self_b = (const float*)d_in[15];
    const float* dec_cross_w= (const float*)d_in[16];
    const float* dec_cross_b= (const float*)d_in[17];
    const float* dec_ffn_w1 = (const float*)d_in[18];
    const float* dec_ffn_b1 = (const float*)d_in[19];
    const float* dec_ffn_w2 = (const float*)d_in[20];
    const float* dec_ffn_b2 = (const float*)d_in[21];
    const float* dec_ln_s   = (const float*)d_in[22];
    const float* dec_ln_b   = (const float*)d_in[23];
    const float* out_w      = (const float*)d_in[24];
    const float* out_b      = (const float*)d_in[25];

    float *h, *tmp, *q, *ffn, *dd, *dq, *dtmp;
    __half *h16, *tmp16, *ffn16, *d16, *dtmp16, *dq16, *qkv16, *kv16;
    __half *wE1, *wE2, *wD1, *wD2, *wQKVe, *wQKVds, *wKVdc;
    __half *wOe, *wOds, *wQdc, *wOdc;
    cudaGetSymbolAddress((void**)&h,      g_h);
    cudaGetSymbolAddress((void**)&tmp,    g_tmp);
    cudaGetSymbolAddress((void**)&q,      g_q);
    cudaGetSymbolAddress((void**)&ffn,    g_ffn);
    cudaGetSymbolAddress((void**)&dd,     g_d);
    cudaGetSymbolAddress((void**)&dq,     g_dq);
    cudaGetSymbolAddress((void**)&dtmp,   g_dtmp);
    cudaGetSymbolAddress((void**)&h16,    g_h16);
    cudaGetSymbolAddress((void**)&tmp16,  g_tmp16);
    cudaGetSymbolAddress((void**)&ffn16,  g_ffn16);
    cudaGetSymbolAddress((void**)&d16,    g_d16);
    cudaGetSymbolAddress((void**)&dtmp16, g_dtmp16);
    cudaGetSymbolAddress((void**)&dq16,   g_dq16);
    cudaGetSymbolAddress((void**)&qkv16,  g_qkv16);
    cudaGetSymbolAddress((void**)&kv16,   g_kv16);
    cudaGetSymbolAddress((void**)&wE1,    g_w16_e1);
    cudaGetSymbolAddress((void**)&wE2,    g_w16_e2);
    cudaGetSymbolAddress((void**)&wD1,    g_w16_d1);
    cudaGetSymbolAddress((void**)&wD2,    g_w16_d2);
    cudaGetSymbolAddress((void**)&wQKVe,  g_wqkv_e);
    cudaGetSymbolAddress((void**)&wQKVds, g_wqkv_ds);
    cudaGetSymbolAddress((void**)&wKVdc,  g_wkv_dc);
    cudaGetSymbolAddress((void**)&wOe,    g_wo_e);
    cudaGetSymbolAddress((void**)&wOds,   g_wo_ds);
    cudaGetSymbolAddress((void**)&wQdc,   g_wq_dc);
    cudaGetSymbolAddress((void**)&wOdc,   g_wo_dc);

    const int Me = Bsz * Ssz;   // 16384
    const int Md = Bsz * Tsz;   // 5760
    const size_t DD = (size_t)Dsz * Dsz;

    cudaFuncSetAttribute(attn_f16, cudaFuncAttributeMaxDynamicSharedMemorySize, ATT_SMEM);
    cudaFuncSetAttribute(gemm_f16, cudaFuncAttributeMaxDynamicSharedMemorySize, GSMEM);
    const int qtE = Ssz / 64;                 // 8
    const int qtD = (Tsz + 63) / 64;          // 3

    const int cw = 6291456;
    f2h_kernel<<<cw / 2048, 256>>>(enc_ffn_w1, wE1, cw);
    f2h_kernel<<<cw / 2048, 256>>>(enc_ffn_w2, wE2, cw);
    f2h_kernel<<<cw / 2048, 256>>>(dec_ffn_w1, wD1, cw);
    f2h_kernel<<<cw / 2048, 256>>>(dec_ffn_w2, wD2, cw);
    f2h_fuse<<<dim3(384, 1, Lsz), 256>>>(enc_attn_w, wQKVe, 0, 3);
    f2h_fuse<<<dim3(128, 1, Lsz), 256>>>(enc_attn_w, wOe, 3, 1);
    f2h_fuse<<<dim3(384, 1, Lsz), 256>>>(dec_self_w, wQKVds, 0, 3);
    f2h_fuse<<<dim3(128, 1, Lsz), 256>>>(dec_self_w, wOds, 3, 1);
    f2h_fuse<<<dim3(128, 1, Lsz), 256>>>(dec_cross_w, wQdc, 0, 1);
    f2h_fuse<<<dim3(256, 1, Lsz), 256>>>(dec_cross_w, wKVdc, 1, 2);
    f2h_fuse<<<dim3(128, 1, Lsz), 256>>>(dec_cross_w, wOdc, 3, 1);

    dim3 blk(256);
    dim3 gE_3D(3 * Dsz / 128, Me / 128);
    dim3 gE_D(Dsz / 128, Me / 128);
    dim3 gE_2D(2 * Dsz / 128, Me / 128);
    dim3 gE_F(Fsz / 128, Me / 128);
    dim3 gD_3D(3 * Dsz / 128, Md / 128);
    dim3 gD_D(Dsz / 128, Md / 128);
    dim3 gD_F(Fsz / 128, Md / 128);
    float* nilF = (float*)0;
    __half* nilH = (__half*)0;

    // ===== encoder =====
    embed_src_kernel<<<Me, 512>>>(x, src_w, src_b, h, h16);
    for (int l = 0; l < Lsz; l++) {
        const __half* wqkv = wQKVe + (size_t)l * Dsz * 3 * Dsz;
        const float* wb = enc_attn_b + (size_t)l * 4 * Dsz;
        gemm_f16<<<gE_3D, blk, GSMEM>>>(h16, wqkv, wb, nilF, qkv16, Me, 3 * Dsz, Dsz, 0);
        attn_f16<<<dim3(qtE, Hsz, Bsz), 256, ATT_SMEM>>>(
            qkv16, 1536, qkv16 + 512, 1536, qkv16 + 1024, 1536, tmp16, Ssz, Ssz, 0);
        gemm_f16<<<gE_D, blk, GSMEM>>>(tmp16, wOe + (size_t)l * DD,
                                       wb + 3 * Dsz, q, nilH, Me, Dsz, Dsz, 0);
        add_ln_kernel<<<Me, 128>>>(h, q, enc_ln_s + (size_t)(l*2)*Dsz,
                                         enc_ln_b + (size_t)(l*2)*Dsz, h16);
        gemm_f16<<<gE_F, blk, GSMEM>>>(h16, wE1 + (size_t)l*Dsz*Fsz,
                                       enc_ffn_b1 + (size_t)l*Fsz, nilF, ffn16, Me, Fsz, Dsz, 1);
        gemm_f16<<<gE_D, blk, GSMEM>>>(ffn16, wE2 + (size_t)l*Fsz*Dsz,
                                       enc_ffn_b2 + (size_t)l*Dsz, tmp, nilH, Me, Dsz, Fsz, 0);
        add_ln_kernel<<<Me, 128>>>(h, tmp, enc_ln_s + (size_t)(l*2+1)*Dsz,
                                           enc_ln_b + (size_t)(l*2+1)*Dsz, h16);
    }

    // ===== decoder =====
    embed_tgt_kernel<<<Md, 512>>>(y, tgt_w, tgt_b, dd, d16);
    for (int l = 0; l < Lsz; l++) {
        const __half* wqkv = wQKVds + (size_t)l * Dsz * 3 * Dsz;
        const float* wb = dec_self_b + (size_t)l * 4 * Dsz;
        gemm_f16<<<gD_3D, blk, GSMEM>>>(d16, wqkv, wb, nilF, qkv16, Md, 3 * Dsz, Dsz, 0);
        attn_f16<<<dim3(qtD, Hsz, Bsz), 256, ATT_SMEM>>>(
            qkv16, 1536, qkv16 + 512, 1536, qkv16 + 1024, 1536, dtmp16, Tsz, Tsz, 1);
        gemm_f16<<<gD_D, blk, GSMEM>>>(dtmp16, wOds + (size_t)l * DD,
                                       wb + 3 * Dsz, dq, nilH, Md, Dsz, Dsz, 0);
        add_ln_kernel<<<Md, 128>>>(dd, dq, dec_ln_s + (size_t)(l*3)*Dsz,
                                           dec_ln_b + (size_t)(l*3)*Dsz, d16);

        const __half* wkv = wKVdc + (size_t)l * Dsz * 2 * Dsz;
        const float* cwb = dec_cross_b + (size_t)l * 4 * Dsz;
        gemm_f16<<<gD_D, blk, GSMEM>>>(d16, wQdc + (size_t)l * DD,
                                       cwb, nilF, dq16, Md, Dsz, Dsz, 0);
        gemm_f16<<<gE_2D, blk, GSMEM>>>(h16, wkv, cwb + Dsz, nilF, kv16, Me, 2 * Dsz, Dsz, 0);
        attn_f16<<<dim3(qtD, Hsz, Bsz), 256, ATT_SMEM>>>(
            dq16, 512, kv16, 1024, kv16 + 512, 1024, dtmp16, Tsz, Ssz, 0);
        gemm_f16<<<gD_D, blk, GSMEM>>>(dtmp16, wOdc + (size_t)l * DD,
                                       cwb + 3 * Dsz, dq, nilH, Md, Dsz, Dsz, 0);
        add_ln_kernel<<<Md, 128>>>(dd, dq, dec_ln_s + (size_t)(l*3+1)*Dsz,
                                           dec_ln_b + (size_t)(l*3+1)*Dsz, d16);

        gemm_f16<<<gD_F, blk, GSMEM>>>(d16, wD1 + (size_t)l*Dsz*Fsz,
                                       dec_ffn_b1 + (size_t)l*Fsz, nilF, ffn16, Md, Fsz, Dsz, 1);
        gemm_f16<<<gD_D, blk, GSMEM>>>(ffn16, wD2 + (size_t)l*Fsz*Dsz,
                                       dec_ffn_b2 + (size_t)l*Dsz, dtmp, nilH, Md, Dsz, Fsz, 0);
        add_ln_kernel<<<Md, 128>>>(dd, dtmp, dec_ln_s + (size_t)(l*3+2)*Dsz,
                                             dec_ln_b + (size_t)(l*3+2)*Dsz, d16);
    }

    out_proj_kernel<<<Md, 128>>>(dd, out_w, out_b, (float*)d_out);
}

// round 17
// speedup vs baseline: 1.0992x; 1.0992x over previous
#include <cuda_runtime.h>
#include <cuda_fp16.h>
#include <math.h>
#include <stdint.h>
#include <string.h>

#define Bsz 32
#define Ssz 512
#define Tsz 180
#define Dsz 512
#define Fsz 2048
#define Lsz 6
#define Hsz 8
#define DHsz 64

// ---------------- scratch (fp32) ----------------
__device__ float g_h   [Bsz*Ssz*Dsz];
__device__ float g_tmp [Bsz*Ssz*Dsz];
__device__ float g_q   [Bsz*Ssz*Dsz];
__device__ float g_ffn [Bsz*Ssz*Fsz];
__device__ float g_d   [Bsz*Tsz*Dsz];
__device__ float g_dq  [Bsz*Tsz*Dsz];
__device__ float g_dtmp[Bsz*Tsz*Dsz];
// ---------------- fp16 shadows ----------------
__device__ __half g_h16   [Bsz*Ssz*Dsz];
__device__ __half g_tmp16 [Bsz*Ssz*Dsz];
__device__ __half g_ffn16 [Bsz*Ssz*Fsz];
__device__ __half g_d16   [Bsz*Tsz*Dsz];
__device__ __half g_dtmp16[Bsz*Tsz*Dsz];
__device__ __half g_dq16  [Bsz*Tsz*Dsz];
__device__ __half g_qkv16 [Bsz*Ssz*3*Dsz];
__device__ __half g_kv16  [Bsz*Ssz*2*Dsz];
// ---------------- fp16 weights ----------------
__device__ __half g_w16_e1[Lsz*Dsz*Fsz];
__device__ __half g_w16_e2[Lsz*Fsz*Dsz];
__device__ __half g_w16_d1[Lsz*Dsz*Fsz];
__device__ __half g_w16_d2[Lsz*Fsz*Dsz];
__device__ __half g_wqkv_e [Lsz*Dsz*3*Dsz];
__device__ __half g_wqkv_ds[Lsz*Dsz*3*Dsz];
__device__ __half g_wkv_dc [Lsz*Dsz*2*Dsz];
__device__ __half g_wo_e  [Lsz*Dsz*Dsz];
__device__ __half g_wo_ds [Lsz*Dsz*Dsz];
__device__ __half g_wq_dc [Lsz*Dsz*Dsz];
__device__ __half g_wo_dc [Lsz*Dsz*Dsz];

// ---------------- helpers ----------------
__device__ __forceinline__ float warpSum(float v) {
    #pragma unroll
    for (int o = 16; o; o >>= 1) v += __shfl_xor_sync(0xffffffffu, v, o);
    return v;
}
__device__ __forceinline__ float warpMax(float v) {
    #pragma unroll
    for (int o = 16; o; o >>= 1) v = fmaxf(v, __shfl_xor_sync(0xffffffffu, v, o));
    return v;
}
__device__ __forceinline__ uint32_t s2u(const void* p) {
    return (uint32_t)__cvta_generic_to_shared(p);
}
__device__ __forceinline__ uint32_t h2u(__half2 h) {
    uint32_t u;
    memcpy(&u, &h, 4);
    return u;
}
__device__ __forceinline__ uint32_t pack_h2(float a, float b) {
    return h2u(__floats2half2_rn(a, b));
}
#define MMA_F16(c, a, b) \
    asm volatile("mma.sync.aligned.m16n8k16.row.col.f32.f16.f16.f32 " \
        "{%0,%1,%2,%3}, {%4,%5,%6,%7}, {%8,%9}, {%0,%1,%2,%3};" \
        : "+f"((c)[0]), "+f"((c)[1]), "+f"((c)[2]), "+f"((c)[3]) \
        : "r"((a)[0]), "r"((a)[1]), "r"((a)[2]), "r"((a)[3]), \
          "r"((b)[0]), "r"((b)[1]))
#define LDSM_X4(r, addr) \
    asm volatile("ldmatrix.sync.aligned.m8n8.x4.shared.b16 {%0,%1,%2,%3}, [%4];" \
        : "=r"((r)[0]), "=r"((r)[1]), "=r"((r)[2]), "=r"((r)[3]) : "r"(addr))
#define LDSM_X4T(r, addr) \
    asm volatile("ldmatrix.sync.aligned.m8n8.x4.trans.shared.b16 {%0,%1,%2,%3}, [%4];" \
        : "=r"((r)[0]), "=r"((r)[1]), "=r"((r)[2]), "=r"((r)[3]) : "r"(addr))
#define CP16(smem_addr, gptr) \
    asm volatile("cp.async.cg.shared.global [%0], [%1], 16;" \
        :: "r"(smem_addr), "l"(gptr) : "memory")
#define CP_COMMIT() asm volatile("cp.async.commit_group;" ::: "memory")
#define CP_WAIT2()  asm volatile("cp.async.wait_group 2;" ::: "memory")

// ---------------- fp32 -> fp16 conversions -------------------------------------------
__global__ __launch_bounds__(256) void f2h_kernel(
    const float* __restrict__ src, __half* __restrict__ dst, int n)
{
    const int i = (blockIdx.x * 256 + threadIdx.x) * 8;
    if (i >= n) return;
    float4 a = *(const float4*)(src + i);
    float4 b = *(const float4*)(src + i + 4);
    uint4 o;
    o.x = pack_h2(a.x, a.y);
    o.y = pack_h2(a.z, a.w);
    o.z = pack_h2(b.x, b.y);
    o.w = pack_h2(b.z, b.w);
    *(uint4*)(dst + i) = o;
}
// fuse nmat [512,512] matrices (starting at matBase within [4,512,512]) into [512, nmat*512]
__global__ __launch_bounds__(256) void f2h_fuse(
    const float* __restrict__ src, __half* __restrict__ dst, int matBase, int nmat)
{
    const int l = blockIdx.z;
    const int rowCols = nmat * 512;
    const int idx = (blockIdx.x * 256 + threadIdx.x) * 8;
    if (idx >= 512 * rowCols) return;
    const int k = idx / rowCols, j = idx % rowCols;
    const int mat = j >> 9, jj = j & 511;
    const float* s = src + (size_t)l * 4 * Dsz * Dsz
                   + (size_t)(matBase + mat) * Dsz * Dsz + k * 512 + jj;
    float4 a = *(const float4*)s;
    float4 b = *(const float4*)(s + 4);
    uint4 o;
    o.x = pack_h2(a.x, a.y);
    o.y = pack_h2(a.z, a.w);
    o.z = pack_h2(b.x, b.y);
    o.w = pack_h2(b.z, b.w);
    *(uint4*)(dst + (size_t)l * 512 * rowCols + idx) = o;
}

// ---------------- FP16 GEMM: cp.async 4-stage pipeline (R14-proven) ------------------
#define ARS 20
#define BRS 68
#define STAGES 4
#define A_STG (128 * ARS)
#define B_STG (32 * BRS)
#define GSMEM ((A_STG + B_STG) * STAGES * 4)

__device__ __forceinline__ void mma_half(uint32_t aAddr, uint32_t bAddr, int kk,
                                         float acc[4][4][4])
{
    uint32_t af[4][4], bf[2][4];
    #pragma unroll
    for (int mt = 0; mt < 4; mt++)
        LDSM_X4(af[mt], aAddr + kk * 32 + mt * 1280);
    #pragma unroll
    for (int nt2 = 0; nt2 < 2; nt2++)
        LDSM_X4T(bf[nt2], bAddr + kk * 4352 + nt2 * 32);
    #pragma unroll
    for (int mt = 0; mt < 4; mt++)
        #pragma unroll
        for (int nt = 0; nt < 4; nt++)
            MMA_F16(acc[mt][nt], af[mt], &bf[nt >> 1][(nt & 1) * 2]);
}

__global__ __launch_bounds__(256, 2) void gemm_f16(
    const __half* __restrict__ A16, const __half* __restrict__ B16,
    const float* __restrict__ bias, float* __restrict__ C,
    __half* __restrict__ C16, int M, int N, int K, int doRelu)
{
    extern __shared__ uint32_t smg[];
    uint32_t* As = smg;
    uint32_t* Bs = smg + STAGES * A_STG;

    const int tid = threadIdx.x, lane = tid & 31, warp = tid >> 5;
    const int g = lane >> 2, t4 = lane & 3;
    const int wm = (warp >> 2) << 6, wn = (warp & 3) << 5;
    const int bm = blockIdx.y << 7, bn = blockIdx.x << 7;

    const int ar  = tid >> 1;
    const int bkr = tid >> 3;
    const __half* aSrc = A16 + (size_t)(bm + ar) * K + ((tid & 1) << 4);
    const __half* bSrc = B16 + (size_t)bkr * N + bn + ((tid & 7) << 4);
    const uint32_t aDst = s2u(&As[ar * ARS + ((tid & 1) << 3)]);
    const uint32_t bDst = s2u(&Bs[bkr * BRS + ((tid & 7) << 3)]);

    const int aRow = wm + ((lane >> 3) & 1) * 8 + (lane & 7);
    const int aCol = (lane >> 4) * 4;
    const int bRow = ((lane >> 3) & 1) * 8 + (lane & 7);
    const int bCol = (wn >> 1) + (lane >> 4) * 4;
    uint32_t aAddrS[STAGES], bAddrS[STAGES];
    #pragma unroll
    for (int s = 0; s < STAGES; s++) {
        aAddrS[s] = s2u(&As[s * A_STG + aRow * ARS + aCol]);
        bAddrS[s] = s2u(&Bs[s * B_STG + bRow * BRS + bCol]);
    }

    const int nc = K >> 5;
    float acc[4][4][4] = {};

    #pragma unroll
    for (int s = 0; s < STAGES - 1; s++) {
        const __half* ap = aSrc + s * 32;
        const __half* bp = bSrc + (size_t)s * 32 * N;
        CP16(aDst + s * (A_STG * 4),      ap);
        CP16(aDst + s * (A_STG * 4) + 16, ap + 8);
        CP16(bDst + s * (B_STG * 4),      bp);
        CP16(bDst + s * (B_STG * 4) + 16, bp + 8);
        CP_COMMIT();
    }
    CP_WAIT2();
    __syncthreads();

    for (int c = 0; c < nc; c++) {
        const int cur = c & (STAGES - 1);
        mma_half(aAddrS[cur], bAddrS[cur], 0, acc);
        mma_half(aAddrS[cur], bAddrS[cur], 1, acc);

        const int nxt = c + STAGES - 1;
        if (nxt < nc) {
            const int s = nxt & (STAGES - 1);
            const __half* ap = aSrc + nxt * 32;
            const __half* bp = bSrc + (size_t)nxt * 32 * N;
            CP16(aDst + s * (A_STG * 4),      ap);
            CP16(aDst + s * (A_STG * 4) + 16, ap + 8);
            CP16(bDst + s * (B_STG * 4),      bp);
            CP16(bDst + s * (B_STG * 4) + 16, bp + 8);
        }
        CP_COMMIT();
        CP_WAIT2();
        __syncthreads();
    }

    #pragma unroll
    for (int mt = 0; mt < 4; mt++) {
        const int gm = bm + wm + mt * 16 + g;
        #pragma unroll
        for (int nt = 0; nt < 4; nt++) {
            const int gn = bn + wn + nt * 8 + (t4 << 1);
            const float b0v = bias[gn], b1v = bias[gn + 1];
            float2 o0 = make_float2(acc[mt][nt][0] + b0v, acc[mt][nt][1] + b1v);
            float2 o1 = make_float2(acc[mt][nt][2] + b0v, acc[mt][nt][3] + b1v);
            if (doRelu) {
                o0.x = fmaxf(o0.x, 0.f); o0.y = fmaxf(o0.y, 0.f);
                o1.x = fmaxf(o1.x, 0.f); o1.y = fmaxf(o1.y, 0.f);
            }
            if (C) {
                *(float2*)(C + (size_t)gm * N + gn)       = o0;
                *(float2*)(C + (size_t)(gm + 8) * N + gn) = o1;
            }
            if (C16) {
                *(uint32_t*)(C16 + (size_t)gm * N + gn)       = pack_h2(o0.x, o0.y);
                *(uint32_t*)(C16 + (size_t)(gm + 8) * N + gn) = pack_h2(o1.x, o1.y);
            }
        }
    }
}

// ---------------- fp16 flash attention (per-tensor row strides) ----------------------
#define ATT_SMEM (13760 * 4)
__global__ __launch_bounds__(256) void attn_f16(
    const __half* __restrict__ Q, int ldq,
    const __half* __restrict__ K, int ldk,
    const __half* __restrict__ V, int ldv,
    __half* __restrict__ O16, int Sq, int Sk, int causal)
{
    extern __shared__ uint32_t sm32[];
    uint32_t* Qs = sm32;
    uint32_t* Ks = sm32 + 2304;
    uint32_t* Vs = sm32 + 4608;
    float*    Ss = (float*)(sm32 + 6912);
    uint32_t* Pb = sm32 + 11264;
    float* m_row = (float*)(sm32 + 13568);
    float* s_row = m_row + 64;
    float* f_row = s_row + 64;

    const int tid = threadIdx.x, lane = tid & 31, w = tid >> 5;
    const int wm = w & 3, wn = w >> 2;
    const int g = lane >> 2, t4 = lane & 3;
    const int qbase = blockIdx.x * 64;
    const int h = blockIdx.y, b = blockIdx.z;
    const size_t hoff = (size_t)h * DHsz;

    const int srow = tid >> 2;
    const int sseg = (tid & 3) << 3;

    {
        const int qg = qbase + srow;
        uint4 v0 = make_uint4(0, 0, 0, 0), v1 = v0;
        if (qg < Sq) {
            const __half* src = Q + (size_t)(b * Sq + qg) * ldq + hoff + (sseg << 1);
            v0 = *(const uint4*)(src);
            v1 = *(const uint4*)(src + 8);
        }
        *(uint4*)&Qs[srow * 36 + sseg]     = v0;
        *(uint4*)&Qs[srow * 36 + sseg + 4] = v1;
    }
    if (tid < 64) { m_row[tid] = -1e30f; s_row[tid] = 0.f; }
    __syncthreads();

    const int aRow = wm * 16 + ((lane >> 3) & 1) * 8 + (lane & 7);
    const int aCol = (lane >> 4) * 4;
    const uint32_t qAddr = s2u(&Qs[aRow * 36 + aCol]);
    uint32_t qf[4][4];
    #pragma unroll
    for (int kc = 0; kc < 4; kc++)
        LDSM_X4(qf[kc], qAddr + kc * 32);

    const uint32_t pAddr = s2u(&Pb[aRow * 36 + aCol]);
    const int bRow = ((lane >> 3) & 1) * 8 + (lane & 7);
    const int bCol = wn * 16 + (lane >> 4) * 4;
    const uint32_t vAddr = s2u(&Vs[bRow * 36 + bCol]);

    float acc_o[4][4] = {};
    const int qend = qbase + 63;
    const int qr = wm * 16 + g;

    for (int c0 = 0; c0 < Sk; c0 += 64) {
        if (causal && c0 > qend) break;
        {
            const int kg = c0 + srow;
            uint4 k0 = make_uint4(0, 0, 0, 0), k1 = k0, v0 = k0, v1 = k0;
            if (kg < Sk) {
                const __half* ks = K + (size_t)(b * Sk + kg) * ldk + hoff + (sseg << 1);
                const __half* vs = V + (size_t)(b * Sk + kg) * ldv + hoff + (sseg << 1);
                k0 = *(const uint4*)(ks); k1 = *(const uint4*)(ks + 8);
                v0 = *(const uint4*)(vs); v1 = *(const uint4*)(vs + 8);
            }
            *(uint4*)&Ks[srow * 36 + sseg]     = k0;
            *(uint4*)&Ks[srow * 36 + sseg + 4] = k1;
            *(uint4*)&Vs[srow * 36 + sseg]     = v0;
            *(uint4*)&Vs[srow * 36 + sseg + 4] = v1;
        }
        __syncthreads();

        float acc_s[4][4] = {};
        #pragma unroll
        for (int kc = 0; kc < 4; kc++) {
            #pragma unroll
            for (int nt = 0; nt < 4; nt++) {
                const int key = wn * 32 + nt * 8 + g;
                uint32_t bf[2];
                bf[0] = Ks[key * 36 + kc * 8 + t4];
                bf[1] = Ks[key * 36 + kc * 8 + t4 + 4];
                MMA_F16(acc_s[nt], qf[kc], bf);
            }
        }
        {
            const int qg0 = qbase + qr, qg1 = qg0 + 8;
            #pragma unroll
            for (int nt = 0; nt < 4; nt++) {
                const int cl = wn * 32 + nt * 8 + (t4 << 1);
                const int kg = c0 + cl;
                float s00 = acc_s[nt][0] * 0.125f, s01 = acc_s[nt][1] * 0.125f;
                float s10 = acc_s[nt][2] * 0.125f, s11 = acc_s[nt][3] * 0.125f;
                if (kg >= Sk || (causal && kg > qg0)) s00 = -1e30f;
                if (kg + 1 >= Sk || (causal && kg + 1 > qg0)) s01 = -1e30f;
                if (kg >= Sk || (causal && kg > qg1)) s10 = -1e30f;
                if (kg + 1 >= Sk || (causal && kg + 1 > qg1)) s11 = -1e30f;
                Ss[qr * 68 + cl] = s00;        Ss[qr * 68 + cl + 1] = s01;
                Ss[(qr + 8) * 68 + cl] = s10;  Ss[(qr + 8) * 68 + cl + 1] = s11;
            }
        }
        __syncthreads();

        #pragma unroll
        for (int rr = 0; rr < 8; rr++) {
            const int r = w * 8 + rr;
            float s0v = Ss[r * 68 + lane];
            float s1v = Ss[r * 68 + lane + 32];
            const float mx = warpMax(fmaxf(s0v, s1v));
            const float mold = m_row[r];
            const float mnew = fmaxf(mold, mx);
            float p0 = __expf(s0v - mnew);
            float p1 = __expf(s1v - mnew);
            const float sum = warpSum(p0 + p1);
            ((__half*)Pb)[r * 72 + lane]      = __float2half_rn(p0);
            ((__half*)Pb)[r * 72 + lane + 32] = __float2half_rn(p1);
            if (lane == 0) {
                const float f = __expf(mold - mnew);
                f_row[r] = f;
                s_row[r] = s_row[r] * f + sum;
                m_row[r] = mnew;
            }
        }
        __syncthreads();

        {
            const float f0 = f_row[qr], f1 = f_row[qr + 8];
            #pragma unroll
            for (int nt = 0; nt < 4; nt++) {
                acc_o[nt][0] *= f0; acc_o[nt][1] *= f0;
                acc_o[nt][2] *= f1; acc_o[nt][3] *= f1;
            }
        }
        #pragma unroll
        for (int kc = 0; kc < 4; kc++) {
            uint32_t pf[4], vf[2][4];
            LDSM_X4(pf, pAddr + kc * 32);
            LDSM_X4T(vf[0], vAddr + kc * 2304);
            LDSM_X4T(vf[1], vAddr + kc * 2304 + 32);
            #pragma unroll
            for (int nt = 0; nt < 4; nt++)
                MMA_F16(acc_o[nt], pf, &vf[nt >> 1][(nt & 1) * 2]);
        }
        __syncthreads();
    }

    const float inv0 = 1.f / s_row[qr];
    const float inv1 = 1.f / s_row[qr + 8];
    const int qg0 = qbase + qr, qg1 = qg0 + 8;
    #pragma unroll
    for (int nt = 0; nt < 4; nt++) {
        const int dcol = wn * 32 + nt * 8 + (t4 << 1);
        if (qg0 < Sq)
            *(uint32_t*)(O16 + (size_t)(b * Sq + qg0) * Dsz + hoff + dcol) =
                pack_h2(acc_o[nt][0] * inv0, acc_o[nt][1] * inv0);
        if (qg1 < Sq)
            *(uint32_t*)(O16 + (size_t)(b * Sq + qg1) * Dsz + hoff + dcol) =
                pack_h2(acc_o[nt][2] * inv1, acc_o[nt][3] * inv1);
    }
}

// ---------------- residual + LayerNorm (+ fp16 copy) --------------------------------
__global__ __launch_bounds__(128) void add_ln_kernel(
    float* __restrict__ h, const float* __restrict__ r,
    const float* __restrict__ scale, const float* __restrict__ bias,
    __half* __restrict__ h16)
{
    const int row = blockIdx.x;
    const int tid = threadIdx.x;
    const int lane = tid & 31, warp = tid >> 5;
    float* hp = h + (size_t)row * Dsz;
    const float* rp = r + (size_t)row * Dsz;

    float4 hv = *(const float4*)(hp + tid * 4);
    float4 rv = *(const float4*)(rp + tid * 4);
    float v0 = hv.x + rv.x, v1 = hv.y + rv.y, v2 = hv.z + rv.z, v3 = hv.w + rv.w;

    float sum = v0 + v1 + v2 + v3;
    float sq  = v0*v0 + v1*v1 + v2*v2 + v3*v3;
    sum = warpSum(sum); sq = warpSum(sq);

    __shared__ float s1[4], s2[4];
    if (lane == 0) { s1[warp] = sum; s2[warp] = sq; }
    __syncthreads();
    sum = s1[0] + s1[1] + s1[2] + s1[3];
    sq  = s2[0] + s2[1] + s2[2] + s2[3];

    const float mu = sum * (1.f / Dsz);
    const float var = sq * (1.f / Dsz) - mu * mu;
    const float rs = rsqrtf(var + 1e-5f);

    float4 sc4 = *(const float4*)(scale + tid * 4);
    float4 bi4 = *(const float4*)(bias + tid * 4);
    float4 o;
    o.x = (v0 - mu) * rs * sc4.x + bi4.x;
    o.y = (v1 - mu) * rs * sc4.y + bi4.y;
    o.z = (v2 - mu) * rs * sc4.z + bi4.z;
    o.w = (v3 - mu) * rs * sc4.w + bi4.w;
    *(float4*)(hp + tid * 4) = o;
    uint2 p;
    p.x = pack_h2(o.x, o.y);
    p.y = pack_h2(o.z, o.w);
    *(uint2*)(h16 + (size_t)row * Dsz + tid * 4) = p;
}

// ---------------- embeddings (+ fp16 copy) -------------------------------------------
__device__ __forceinline__ float pos_enc(int pos, int d) {
    const int i2 = d & ~1;
    const float freq = expf(-(float)i2 * (9.210340371976184f / 512.f));
    const float ang = (float)pos * freq;
    return (d & 1) ? cosf(ang) : sinf(ang);
}
__global__ __launch_bounds__(512) void embed_src_kernel(
    const float* __restrict__ x, const float* __restrict__ w,
    const float* __restrict__ b, float* __restrict__ h, __half* __restrict__ h16)
{
    const int token = blockIdx.x;
    const int d = threadIdx.x;
    const int s = token % Ssz;
    const float x0 = x[token * 2 + 0], x1 = x[token * 2 + 1];
    const float val = x0 * w[d] + x1 * w[Dsz + d] + b[d] + pos_enc(s, d);
    h[(size_t)token * Dsz + d] = val;
    h16[(size_t)token * Dsz + d] = __float2half_rn(val);
}
__global__ __launch_bounds__(512) void embed_tgt_kernel(
    const float* __restrict__ y, const float* __restrict__ w,
    const float* __restrict__ b, float* __restrict__ dd, __half* __restrict__ d16)
{
    const int token = blockIdx.x;
    const int d = threadIdx.x;
    const int bb = token / Tsz, t = token % Tsz;
    const float val = (t == 0) ? 0.f : y[bb * Tsz + (t - 1)];
    const float o = val * w[d] + b[d] + pos_enc(t, d);
    dd[(size_t)token * Dsz + d] = o;
    d16[(size_t)token * Dsz + d] = __float2half_rn(o);
}

// ---------------- final projection ---------------------------------------------------
__global__ __launch_bounds__(128) void out_proj_kernel(
    const float* __restrict__ dd, const float* __restrict__ w,
    const float* __restrict__ b, float* __restrict__ out)
{
    const int token = blockIdx.x;
    const int tid = threadIdx.x;
    const int lane = tid & 31, warp = tid >> 5;
    float s = 0.f;
    for (int i = tid; i < Dsz; i += 128)
        s += dd[(size_t)token * Dsz + i] * w[i];
    s = warpSum(s);
    __shared__ float smr[4];
    if (lane == 0) smr[warp] = s;
    __syncthreads();
    if (tid == 0) out[token] = smr[0] + smr[1] + smr[2] + smr[3] + b[0];
}

// ---------------- host orchestration -------------------------------------------------
extern "C" void kernel_launch(void* const* d_in, const int* in_sizes, int n_in,
                              void* d_out, int out_size)
{
    const float* x          = (const float*)d_in[0];
    const float* y          = (const float*)d_in[1];
    const float* src_w      = (const float*)d_in[2];
    const float* src_b      = (const float*)d_in[3];
    const float* tgt_w      = (const float*)d_in[4];
    const float* tgt_b      = (const float*)d_in[5];
    const float* enc_attn_w = (const float*)d_in[6];
    const float* enc_attn_b = (const float*)d_in[7];
    const float* enc_ffn_w1 = (const float*)d_in[8];
    const float* enc_ffn_b1 = (const float*)d_in[9];
    const float* enc_ffn_w2 = (const float*)d_in[10];
    const float* enc_ffn_b2 = (const float*)d_in[11];
    const float* enc_ln_s   = (const float*)d_in[12];
    const float* enc_ln_b   = (const float*)d_in[13];
    const float* dec_self_w = (const float*)d_in[14];
    const float* dec_self_b = (const float*)d_in[15];
    const float* dec_cross_w= (const float*)d_in[16];
    const float* dec_cross_b= (const float*)d_in[17];
    const float* dec_ffn_w1 = (const float*)d_in[18];
    const float* dec_ffn_b1 = (const float*)d_in[19];
    const float* dec_ffn_w2 = (const float*)d_in[20];
    const float* dec_ffn_b2 = (const float*)d_in[21];
    const float* dec_ln_s   = (const float*)d_in[22];
    const float* dec_ln_b   = (const float*)d_in[23];
    const float* out_w      = (const float*)d_in[24];
    const float* out_b      = (const float*)d_in[25];

    float *h, *tmp, *q, *ffn, *dd, *dq, *dtmp;
    __half *h16, *tmp16, *ffn16, *d16, *dtmp16, *dq16, *qkv16, *kv16;
    __half *wE1, *wE2, *wD1, *wD2, *wQKVe, *wQKVds, *wKVdc;
    __half *wOe, *wOds, *wQdc, *wOdc;
    cudaGetSymbolAddress((void**)&h,      g_h);
    cudaGetSymbolAddress((void**)&tmp,    g_tmp);
    cudaGetSymbolAddress((void**)&q,      g_q);
    cudaGetSymbolAddress((void**)&ffn,    g_ffn);
    cudaGetSymbolAddress((void**)&dd,     g_d);
    cudaGetSymbolAddress((void**)&dq,     g_dq);
    cudaGetSymbolAddress((void**)&dtmp,   g_dtmp);
    cudaGetSymbolAddress((void**)&h16,    g_h16);
    cudaGetSymbolAddress((void**)&tmp16,  g_tmp16);
    cudaGetSymbolAddress((void**)&ffn16,  g_ffn16);
    cudaGetSymbolAddress((void**)&d16,    g_d16);
    cudaGetSymbolAddress((void**)&dtmp16, g_dtmp16);
    cudaGetSymbolAddress((void**)&dq16,   g_dq16);
    cudaGetSymbolAddress((void**)&qkv16,  g_qkv16);
    cudaGetSymbolAddress((void**)&kv16,   g_kv16);
    cudaGetSymbolAddress((void**)&wE1,    g_w16_e1);
    cudaGetSymbolAddress((void**)&wE2,    g_w16_e2);
    cudaGetSymbolAddress((void**)&wD1,    g_w16_d1);
    cudaGetSymbolAddress((void**)&wD2,    g_w16_d2);
    cudaGetSymbolAddress((void**)&wQKVe,  g_wqkv_e);
    cudaGetSymbolAddress((void**)&wQKVds, g_wqkv_ds);
    cudaGetSymbolAddress((void**)&wKVdc,  g_wkv_dc);
    cudaGetSymbolAddress((void**)&wOe,    g_wo_e);
    cudaGetSymbolAddress((void**)&wOds,   g_wo_ds);
    cudaGetSymbolAddress((void**)&wQdc,   g_wq_dc);
    cudaGetSymbolAddress((void**)&wOdc,   g_wo_dc);

    const int Me = Bsz * Ssz;   // 16384
    const int Md = Bsz * Tsz;   // 5760
    const size_t DD = (size_t)Dsz * Dsz;

    cudaFuncSetAttribute(attn_f16, cudaFuncAttributeMaxDynamicSharedMemorySize, ATT_SMEM);
    cudaFuncSetAttribute(gemm_f16, cudaFuncAttributeMaxDynamicSharedMemorySize, GSMEM);
    const int qtE = Ssz / 64;                 // 8
    const int qtD = (Tsz + 63) / 64;          // 3

    const int cw = 6291456;
    f2h_kernel<<<cw / 2048, 256>>>(enc_ffn_w1, wE1, cw);
    f2h_kernel<<<cw / 2048, 256>>>(enc_ffn_w2, wE2, cw);
    f2h_kernel<<<cw / 2048, 256>>>(dec_ffn_w1, wD1, cw);
    f2h_kernel<<<cw / 2048, 256>>>(dec_ffn_w2, wD2, cw);
    f2h_fuse<<<dim3(384, 1, Lsz), 256>>>(enc_attn_w, wQKVe, 0, 3);
    f2h_fuse<<<dim3(128, 1, Lsz), 256>>>(enc_attn_w, wOe, 3, 1);
    f2h_fuse<<<dim3(384, 1, Lsz), 256>>>(dec_self_w, wQKVds, 0, 3);
    f2h_fuse<<<dim3(128, 1, Lsz), 256>>>(dec_self_w, wOds, 3, 1);
    f2h_fuse<<<dim3(128, 1, Lsz), 256>>>(dec_cross_w, wQdc, 0, 1);
    f2h_fuse<<<dim3(256, 1, Lsz), 256>>>(dec_cross_w, wKVdc, 1, 2);
    f2h_fuse<<<dim3(128, 1, Lsz), 256>>>(dec_cross_w, wOdc, 3, 1);

    dim3 blk(256);
    dim3 gE_3D(3 * Dsz / 128, Me / 128);
    dim3 gE_D(Dsz / 128, Me / 128);
    dim3 gE_2D(2 * Dsz / 128, Me / 128);
    dim3 gE_F(Fsz / 128, Me / 128);
    dim3 gD_3D(3 * Dsz / 128, Md / 128);
    dim3 gD_D(Dsz / 128, Md / 128);
    dim3 gD_F(Fsz / 128, Md / 128);
    float* nilF = (float*)0;
    __half* nilH = (__half*)0;

    // ===== encoder =====
    embed_src_kernel<<<Me, 512>>>(x, src_w, src_b, h, h16);
    for (int l = 0; l < Lsz; l++) {
        const __half* wqkv = wQKVe + (size_t)l * Dsz * 3 * Dsz;
        const float* wb = enc_attn_b + (size_t)l * 4 * Dsz;
        gemm_f16<<<gE_3D, blk, GSMEM>>>(h16, wqkv, wb, nilF, qkv16, Me, 3 * Dsz, Dsz, 0);
        attn_f16<<<dim3(qtE, Hsz, Bsz), 256, ATT_SMEM>>>(
            qkv16, 1536, qkv16 + 512, 1536, qkv16 + 1024, 1536, tmp16, Ssz, Ssz, 0);
        gemm_f16<<<gE_D, blk, GSMEM>>>(tmp16, wOe + (size_t)l * DD,
                                       wb + 3 * Dsz, q, nilH, Me, Dsz, Dsz, 0);
        add_ln_kernel<<<Me, 128>>>(h, q, enc_ln_s + (size_t)(l*2)*Dsz,
                                         enc_ln_b + (size_t)(l*2)*Dsz, h16);
        gemm_f16<<<gE_F, blk, GSMEM>>>(h16, wE1 + (size_t)l*Dsz*Fsz,
                                       enc_ffn_b1 + (size_t)l*Fsz, nilF, ffn16, Me, Fsz, Dsz, 1);
        gemm_f16<<<gE_D, blk, GSMEM>>>(ffn16, wE2 + (size_t)l*Fsz*Dsz,
                                       enc_ffn_b2 + (size_t)l*Dsz, tmp, nilH, Me, Dsz, Fsz, 0);
        add_ln_kernel<<<Me, 128>>>(h, tmp, enc_ln_s + (size_t)(l*2+1)*Dsz,
                                           enc_ln_b + (size_t)(l*2+1)*Dsz, h16);
    }

    // ===== decoder =====
    embed_tgt_kernel<<<Md, 512>>>(y, tgt_w, tgt_b, dd, d16);
    for (int l = 0; l < Lsz; l++) {
        const __half* wqkv = wQKVds + (size_t)l * Dsz * 3 * Dsz;
        const float* wb = dec_self_b + (size_t)l * 4 * Dsz;
        gemm_f16<<<gD_3D, blk, GSMEM>>>(d16, wqkv, wb, nilF, qkv16, Md, 3 * Dsz, Dsz, 0);
        attn_f16<<<dim3(qtD, Hsz, Bsz), 256, ATT_SMEM>>>(
            qkv16, 1536, qkv16 + 512, 1536, qkv16 + 1024, 1536, dtmp16, Tsz, Tsz, 1);
        gemm_f16<<<gD_D, blk, GSMEM>>>(dtmp16, wOds + (size_t)l * DD,
                                       wb + 3 * Dsz, dq, nilH, Md, Dsz, Dsz, 0);
        add_ln_kernel<<<Md, 128>>>(dd, dq, dec_ln_s + (size_t)(l*3)*Dsz,
                                           dec_ln_b + (size_t)(l*3)*Dsz, d16);

        const __half* wkv = wKVdc + (size_t)l * Dsz * 2 * Dsz;
        const float* cwb = dec_cross_b + (size_t)l * 4 * Dsz;
        gemm_f16<<<gD_D, blk, GSMEM>>>(d16, wQdc + (size_t)l * DD,
                                       cwb, nilF, dq16, Md, Dsz, Dsz, 0);
        gemm_f16<<<gE_2D, blk, GSMEM>>>(h16, wkv, cwb + Dsz, nilF, kv16, Me, 2 * Dsz, Dsz, 0);
        attn_f16<<<dim3(qtD, Hsz, Bsz), 256, ATT_SMEM>>>(
            dq16, 512, kv16, 1024, kv16 + 512, 1024, dtmp16, Tsz, Ssz, 0);
        gemm_f16<<<gD_D, blk, GSMEM>>>(dtmp16, wOdc + (size_t)l * DD,
                                       cwb + 3 * Dsz, dq, nilH, Md, Dsz, Dsz, 0);
        add_ln_kernel<<<Md, 128>>>(dd, dq, dec_ln_s + (size_t)(l*3+1)*Dsz,
                                           dec_ln_b + (size_t)(l*3+1)*Dsz, d16);

        gemm_f16<<<gD_F, blk, GSMEM>>>(d16, wD1 + (size_t)l*Dsz*Fsz,
                                       dec_ffn_b1 + (size_t)l*Fsz, nilF, ffn16, Md, Fsz, Dsz, 1);
        gemm_f16<<<gD_D, blk, GSMEM>>>(ffn16, wD2 + (size_t)l*Fsz*Dsz,
                                       dec_ffn_b2 + (size_t)l*Dsz, dtmp, nilH, Md, Dsz, Fsz, 0);
        add_ln_kernel<<<Md, 128>>>(dd, dtmp, dec_ln_s + (size_t)(l*3+2)*Dsz,
                                             dec_ln_b + (size_t)(l*3+2)*Dsz, d16);
    }

    out_proj_kernel<<<Md, 128>>>(dd, out_w, out_b, (float*)d_out);
}